// round 15
// baseline (speedup 1.0000x reference)
#include <cuda_runtime.h>
#include <cuda_bf16.h>
#include <stdint.h>
#include <math.h>

#define MAXN 50000
#define MAXE 800000

// ---- device scratch (allocation-free rule) ----
__device__ float g_P[MAXN * 64];      // s @ ng_w1[0:64]
__device__ float g_z[MAXN * 128];     // segsum(silu(hm))
__device__ float g_vagg[MAXN * 3];
__device__ float g_deg[MAXN];
__device__ float g_Wpt[128 * 192];    // fused W' transposed: [o][r]
__device__ float g_b1p[128];          // fused bias into hm
__device__ float g_q[128];            // mg_w2 @ pe_w
__device__ float g_qb[1];             // b_mg2 @ pe_w + pe_b

__device__ __forceinline__ float siluf(float x) { return x / (1.0f + __expf(-x)); }

__device__ __forceinline__ void reds(float* p, float v) {
    asm volatile("red.global.add.f32 [%0], %1;" :: "l"(p), "f"(v) : "memory");
}
__device__ __forceinline__ void redv2(float* p, float a, float b) {
    asm volatile("red.global.add.v2.f32 [%0], {%1,%2};"
                 :: "l"(p), "f"(a), "f"(b) : "memory");
}
__device__ __forceinline__ void barg(int id) {
    asm volatile("bar.sync %0, 128;" :: "r"(id) : "memory");
}

// ---- warp MMA helpers (sm_80+ vocabulary, safe on compute_103) ----
__device__ __forceinline__ uint32_t smem_u32(const void* p) {
    uint32_t a;
    asm("{ .reg .u64 t; cvta.to.shared.u64 t, %1; cvt.u32.u64 %0, t; }" : "=r"(a) : "l"(p));
    return a;
}
__device__ __forceinline__ void mma_bf16(float* d, const uint32_t* a, const uint32_t* b) {
    asm volatile(
        "mma.sync.aligned.m16n8k16.row.col.f32.bf16.bf16.f32 "
        "{%0,%1,%2,%3}, {%4,%5,%6,%7}, {%8,%9}, {%0,%1,%2,%3};"
        : "+f"(d[0]), "+f"(d[1]), "+f"(d[2]), "+f"(d[3])
        : "r"(a[0]), "r"(a[1]), "r"(a[2]), "r"(a[3]), "r"(b[0]), "r"(b[1]));
}
__device__ __forceinline__ void ldsm4(uint32_t* r, uint32_t addr) {
    asm volatile("ldmatrix.sync.aligned.m8n8.x4.shared.b16 {%0,%1,%2,%3}, [%4];"
                 : "=r"(r[0]), "=r"(r[1]), "=r"(r[2]), "=r"(r[3]) : "r"(addr));
}
__device__ __forceinline__ uint32_t sw(uint32_t b) { return b ^ ((b >> 3) & 0x70u); }

// blocked-atom SW128 byte offset in a [rows x cols] bf16 tile with 64-col atoms,
// 16 row-atoms per col-atom. atom = 8 rows x 64 cols (128B wide).
__device__ __forceinline__ uint32_t xoff(int row, int col) {
    uint32_t b = (uint32_t)((row >> 3) + (col >> 6) * 16) * 1024u
               + (uint32_t)(row & 7) * 128u + (uint32_t)(col & 63) * 2u;
    return sw(b);
}
// split-store an adjacent col pair (packed bf16x2, single STS.32 per tile)
__device__ __forceinline__ void store_pair(char* ah, char* al, uint32_t o, float x, float y) {
    __nv_bfloat162 h = __floats2bfloat162_rn(x, y);
    __nv_bfloat162 l = __floats2bfloat162_rn(x - __bfloat162float(h.x),
                                             y - __bfloat162float(h.y));
    *(__nv_bfloat162*)(ah + o) = h;
    *(__nv_bfloat162*)(al + o) = l;
}

// ---- smem layout (bytes) ----
#define OFF_AH 0           // X tile hi: 128 rows x 192 cols bf16 (3 col-atoms)
#define OFF_AL 49152
#define OFF_BH 98304       // W' tile hi: 128 out x 192 k bf16
#define OFF_BL 147456
#define OFF_EGBH 196608    // eg_w1 B-tile hi: 64 out x 64 k bf16 (8KB)
#define OFF_EGBL 204800
#define OFF_Q 212992       // float[128]
#define OFF_B1P 213504     // float[128]
#define OFF_W64S 214016    // float[64]  eg_w1 row 64 (cross coeff)
#define OFF_BEGS 214272    // float[64]  eg bias
#define OFF_W65 214528     // float[64]  ng_w1 row 64
#define OFF_BNG 214784     // float[64]  ng bias
#define OFF_RESI 215040    // float[128]
#define OFF_RESJ 215552
#define OFF_CROSS 216064   // float[128]
#define OFF_EVU 216576     // float[128][3]
#define OFF_EROW 218112    // int[128]
#define OFF_ECOL 218624    // int[128]
#define OFF_VALID 219136   // int[128]
#define OFF_QB 219648
#define EDGE_SMEM_TOTAL 219656

// ---------------------------------------------------------------- zero scratch
__global__ void zero_kernel(int n128, int n3, int n1) {
    int i = blockIdx.x * blockDim.x + threadIdx.x;
    int stride = gridDim.x * blockDim.x;
    for (int k = i; k < n128; k += stride) g_z[k] = 0.0f;
    for (int k = i; k < n3; k += stride) g_vagg[k] = 0.0f;
    for (int k = i; k < n1; k += stride) g_deg[k] = 0.0f;
}

// ---------------------------------------------------------------- P = s @ ng_w1[0:64,:]
__global__ __launch_bounds__(256) void pre_kernel(const float* __restrict__ s,
                                                  const float* __restrict__ ngw1, int N) {
    __shared__ float wt[64][68];
    __shared__ float xs[4][68];
    const int tid = threadIdx.x;
    for (int idx = tid; idx < 64 * 64; idx += 256) {
        int k = idx >> 6, f = idx & 63;
        wt[f][k] = ngw1[idx];
    }
    __syncthreads();
    const int slot = tid >> 6, f = tid & 63;
    for (int n0 = blockIdx.x * 4; n0 < N; n0 += gridDim.x * 4) {
        int n = n0 + slot;
        xs[slot][f] = (n < N) ? s[n * 64 + f] : 0.0f;
        __syncthreads();
        float acc = 0.0f;
#pragma unroll 4
        for (int k = 0; k < 64; k += 4) {
            float4 w = *(const float4*)&wt[f][k];
            float4 x = *(const float4*)&xs[slot][k];
            acc += w.x * x.x + w.y * x.y + w.z * x.z + w.w * x.w;
        }
        if (n < N) g_P[n * 64 + f] = acc;
        __syncthreads();
    }
}

// ---------------------------------------------------------------- fold weights
__global__ void preW_kernel(const float* __restrict__ ngw2, const float* __restrict__ ngb2,
                            const float* __restrict__ egw2, const float* __restrict__ egb2,
                            const float* __restrict__ mgw1, const float* __restrict__ mgb1,
                            const float* __restrict__ mgw2, const float* __restrict__ mgb2,
                            const float* __restrict__ pew, const float* __restrict__ peb) {
    int idx = blockIdx.x * blockDim.x + threadIdx.x;
    int stride = gridDim.x * blockDim.x;
    for (int t = idx; t < 128 * 192 + 128 + 128 + 1; t += stride) {
        if (t < 128 * 192) {
            int o = t / 192, r = t % 192;
            int seg = r >> 6, rr = r & 63, koff = seg * 64;
            const float* src = (seg < 2) ? ngw2 : egw2;
            float val = 0.0f;
            for (int k = 0; k < 64; k++)
                val += src[rr * 64 + k] * mgw1[(koff + k) * 128 + o];
            g_Wpt[o * 192 + r] = val;
        } else if (t < 128 * 192 + 128) {
            int o = t - 128 * 192;
            float val = mgb1[o];
            for (int k = 0; k < 64; k++) {
                val += ngb2[k] * (mgw1[k * 128 + o] + mgw1[(64 + k) * 128 + o]);
                val += egb2[k] * mgw1[(128 + k) * 128 + o];
            }
            g_b1p[o] = val;
        } else if (t < 128 * 192 + 256) {
            int o = t - 128 * 192 - 128;
            float val = 0.0f;
            for (int j = 0; j < 64; j++) val += mgw2[o * 64 + j] * pew[j];
            g_q[o] = val;
        } else {
            float val = peb[0];
            for (int j = 0; j < 64; j++) val += mgb2[j] * pew[j];
            g_qb[0] = val;
        }
    }
}

// ---------------------------------------------------------------- fused edge kernel
// Persistent CTA, 512 threads = 4 independent 4-warp groups (named barrier 1+g).
// Per tile: P0/A1 -> bar -> B1(h_e MMA) -> B2a(kf0-7, atoms 0/1 only; hides B1
// latency + barrier skew) -> bar -> E1(silu h_e -> atom2) -> bar -> B2b(kf8-11)
// -> C epilogue -> bar.
__global__ __launch_bounds__(512, 1) void edge_kernel(
    const float* __restrict__ v, const int* __restrict__ ei,
    const float* __restrict__ ea, const float* __restrict__ evu,
    const float* __restrict__ ngw1, const float* __restrict__ ngb1,
    const float* __restrict__ egw1, const float* __restrict__ egb1,
    int N, int E) {
    extern __shared__ char smem[];
    char* AH = smem + OFF_AH;
    char* AL = smem + OFF_AL;
    float* qs = (float*)(smem + OFF_Q);
    float* b1ps = (float*)(smem + OFF_B1P);
    float* w64s = (float*)(smem + OFF_W64S);
    float* begs = (float*)(smem + OFF_BEGS);
    float* w65s = (float*)(smem + OFF_W65);
    float* bng = (float*)(smem + OFF_BNG);
    float* resIs = (float*)(smem + OFF_RESI);
    float* resJs = (float*)(smem + OFF_RESJ);
    float* crossms = (float*)(smem + OFF_CROSS);
    float* evus = (float*)(smem + OFF_EVU);
    int* eRow = (int*)(smem + OFF_EROW);
    int* eCol = (int*)(smem + OFF_ECOL);
    int* valid = (int*)(smem + OFF_VALID);
    float* qbp = (float*)(smem + OFF_QB);

    const int tid = threadIdx.x;
    const int lane = tid & 31;
    const int w = tid >> 5;
    const int L = lane;
    const uint32_t sbase = smem_u32(smem);

    // ---- one-time staging ----
    for (int idx = tid; idx < 128 * 192; idx += 512) {
        int o = idx / 192, r = idx % 192;
        float val = g_Wpt[idx];
        uint32_t off = xoff(o, r);
        __nv_bfloat16 h = __float2bfloat16(val);
        *(__nv_bfloat16*)(smem + OFF_BH + off) = h;
        *(__nv_bfloat16*)(smem + OFF_BL + off) = __float2bfloat16(val - __bfloat162float(h));
    }
    for (int idx = tid; idx < 64 * 64; idx += 512) {
        int k = idx >> 6, n = idx & 63;
        float val = egw1[k * 64 + n];   // B[n][k] = W1[k][n]
        uint32_t off = sw((uint32_t)((n >> 3) * 1024 + (n & 7) * 128 + k * 2));
        __nv_bfloat16 h = __float2bfloat16(val);
        *(__nv_bfloat16*)(smem + OFF_EGBH + off) = h;
        *(__nv_bfloat16*)(smem + OFF_EGBL + off) = __float2bfloat16(val - __bfloat162float(h));
    }
    if (tid < 64) {
        w64s[tid] = egw1[64 * 64 + tid];
        begs[tid] = egb1[tid];
        w65s[tid] = ngw1[64 * 64 + tid];
        bng[tid] = ngb1[tid];
    } else if (tid < 192) {
        b1ps[tid - 64] = g_b1p[tid - 64];
    } else if (tid < 320) {
        qs[tid - 192] = g_q[tid - 192];
    } else if (tid == 320) {
        qbp[0] = g_qb[0];
    }
    __syncthreads();

    // group decomposition: 4 groups x 4 warps
    const int g = w >> 2;            // 0..3
    const int wh = w & 3;            // warp within group
    const int g32 = g * 32;
    const int barid = 1 + g;

    // hoisted per-lane constants (phase A)
    const float w65a = w65s[2 * L], w65b = w65s[2 * L + 1];
    const float bna = bng[2 * L], bnb = bng[2 * L + 1];

    // warp-tile constants
    const int mbase = g32;                   // all 4 warps share the group's 32 edges
    const int ncol = wh;                     // B2: N group of 32
    const int nb1 = wh * 16;                 // B1: N group of 16
    const int gID = lane >> 2, tig = lane & 3;
    const int g8 = lane >> 3;
    uint32_t arow[2];
#pragma unroll
    for (int mb = 0; mb < 2; mb++) {
        int row = mbase + mb * 16 + (lane & 15);
        arow[mb] = (uint32_t)((row >> 3) * 1024 + (row & 7) * 128);
    }
    const uint32_t acoll = (uint32_t)((lane >> 4) * 8);
    uint32_t brow4[2];
#pragma unroll
    for (int p = 0; p < 2; p++) {
        int row = ncol * 32 + p * 16 + (g8 >> 1) * 8 + (lane & 7);
        brow4[p] = (uint32_t)((row >> 3) * 1024 + (row & 7) * 128);
    }
    const uint32_t bk4 = (uint32_t)((g8 & 1) * 8);
    uint32_t browE4;
    {
        int nrow = nb1 + (g8 >> 1) * 8 + (lane & 7);
        browE4 = (uint32_t)((nrow >> 3) * 1024 + (nrow & 7) * 128);
    }
    const float qb4 = 0.25f * qbp[0];
    const int stride = gridDim.x * 128;
    const int erow0 = g32 + wh * 8;          // this warp's first edge row

    for (int base = blockIdx.x * 128; base < E; base += stride) {
        // ---- P0 (warp-local): metadata for this warp's 8 edges ----
        if (L < 8) {
            int erow = erow0 + L;
            int e = base + erow;
            int ok = (e < E);
            int r = 0, c = 0;
            float rI = 0.f, rJ = 0.f, cm = 0.f, u0 = 0.f, u1 = 0.f, u2 = 0.f;
            if (ok) {
                r = ei[e]; c = ei[E + e];
                float vx = v[r * 3 + 0], vy = v[r * 3 + 1], vz = v[r * 3 + 2];
                float wx = v[c * 3 + 0], wy = v[c * 3 + 1], wz = v[c * 3 + 2];
                u0 = evu[e * 3 + 0]; u1 = evu[e * 3 + 1]; u2 = evu[e * 3 + 2];
                rI = 1.0f - (vx * u0 + vy * u1 + vz * u2);
                rJ = 1.0f + (wx * u0 + wy * u1 + wz * u2);
                float cx = vy * wz - vz * wy;
                float cy = vz * wx - vx * wz;
                float cz = vx * wy - vy * wx;
                cm = sqrtf(cx * cx + cy * cy + cz * cz);
            }
            valid[erow] = ok;
            eRow[erow] = r;
            eCol[erow] = c;
            resIs[erow] = rI; resJs[erow] = rJ; crossms[erow] = cm;
            evus[erow * 3 + 0] = u0;
            evus[erow * 3 + 1] = u1;
            evus[erow * 3 + 2] = u2;
        }
        __syncwarp();

        // ---- A1: stage ea into X atom2 + h_i/h_j into atoms 0/1 ----
#pragma unroll
        for (int j = 0; j < 8; j++) {
            int erow = erow0 + j;
            int e = base + erow;
            float2 a = make_float2(0.f, 0.f);
            if (e < E) a = *(const float2*)&ea[(size_t)e * 64 + 2 * L];
            uint32_t o = sw(32768u + (uint32_t)((erow >> 3) * 1024 + (erow & 7) * 128 + 4 * L));
            store_pair(AH, AL, o, a.x, a.y);
        }
#pragma unroll
        for (int j = 0; j < 8; j++) {
            int erow = erow0 + j;
            int ok = valid[erow];
            float2 pi = make_float2(0.f, 0.f), pj = pi;
            if (ok) {
                int r = eRow[erow], c = eCol[erow];
                pi = *(const float2*)&g_P[r * 64 + 2 * L];
                pj = *(const float2*)&g_P[c * 64 + 2 * L];
            }
            float rI = resIs[erow], rJ = resJs[erow];
            float i0 = siluf(pi.x + rI * w65a + bna);
            float i1 = siluf(pi.y + rI * w65b + bnb);
            float j0v = siluf(pj.x + rJ * w65a + bna);
            float j1v = siluf(pj.y + rJ * w65b + bnb);
            uint32_t ro = (uint32_t)((erow >> 3) * 1024 + (erow & 7) * 128 + 4 * L);
            store_pair(AH, AL, sw(ro), i0, i1);
            store_pair(AH, AL, sw(16384u + ro), j0v, j1v);
        }
        barg(barid);

        // ---- B1: h_e MMA (32 edges x 16 out-cols, K=64, 3 split terms) ----
        float dE[2][2][4];
#pragma unroll
        for (int mb = 0; mb < 2; mb++)
#pragma unroll
            for (int nf = 0; nf < 2; nf++)
#pragma unroll
                for (int i = 0; i < 4; i++) dE[mb][nf][i] = 0.0f;
#pragma unroll
        for (int kf = 0; kf < 4; kf++) {
            uint32_t ac2 = (uint32_t)(kf * 16 + acoll) * 2;
            uint32_t ah0[4], ah1[4], al0[4], al1[4];
            ldsm4(ah0, sbase + OFF_AH + sw(32768u + arow[0] + ac2));
            ldsm4(ah1, sbase + OFF_AH + sw(32768u + arow[1] + ac2));
            ldsm4(al0, sbase + OFF_AL + sw(32768u + arow[0] + ac2));
            ldsm4(al1, sbase + OFF_AL + sw(32768u + arow[1] + ac2));
            uint32_t bc2 = (uint32_t)(kf * 16 + bk4) * 2;
            uint32_t bh4[4], bl4[4];
            ldsm4(bh4, sbase + OFF_EGBH + sw(browE4 + bc2));
            ldsm4(bl4, sbase + OFF_EGBL + sw(browE4 + bc2));
#pragma unroll
            for (int sub = 0; sub < 2; sub++) {
                uint32_t* bh = &bh4[2 * sub];
                uint32_t* bl = &bl4[2 * sub];
                mma_bf16(dE[0][sub], ah0, bh);
                mma_bf16(dE[1][sub], ah1, bh);
                mma_bf16(dE[0][sub], ah0, bl);
                mma_bf16(dE[1][sub], ah1, bl);
                mma_bf16(dE[0][sub], al0, bh);
                mma_bf16(dE[1][sub], al1, bh);
            }
        }

        // ---- B2a: big GEMM kf 0..7 (atoms 0/1 only) — hides B1 latency ----
        float d[2][4][4];
#pragma unroll
        for (int mb = 0; mb < 2; mb++)
#pragma unroll
            for (int nf = 0; nf < 4; nf++)
#pragma unroll
                for (int i = 0; i < 4; i++) d[mb][nf][i] = 0.0f;
#pragma unroll
        for (int kf = 0; kf < 8; kf++) {
            uint32_t acol = (uint32_t)kf * 16 + acoll;
            uint32_t acp = (acol >> 6) * 16384 + (acol & 63) * 2;
            uint32_t ah0[4], ah1[4], al0[4], al1[4];
            ldsm4(ah0, sbase + OFF_AH + sw(arow[0] + acp));
            ldsm4(ah1, sbase + OFF_AH + sw(arow[1] + acp));
            ldsm4(al0, sbase + OFF_AL + sw(arow[0] + acp));
            ldsm4(al1, sbase + OFF_AL + sw(arow[1] + acp));
            uint32_t bcol = (uint32_t)kf * 16 + bk4;
            uint32_t bcp = (bcol >> 6) * 16384 + (bcol & 63) * 2;
#pragma unroll
            for (int p = 0; p < 2; p++) {
                uint32_t bh4[4], bl4[4];
                ldsm4(bh4, sbase + OFF_BH + sw(brow4[p] + bcp));
                ldsm4(bl4, sbase + OFF_BL + sw(brow4[p] + bcp));
#pragma unroll
                for (int sub = 0; sub < 2; sub++) {
                    int nf = 2 * p + sub;
                    uint32_t* bh = &bh4[2 * sub];
                    uint32_t* bl = &bl4[2 * sub];
                    mma_bf16(d[0][nf], ah0, bh);
                    mma_bf16(d[1][nf], ah1, bh);
                    mma_bf16(d[0][nf], ah0, bl);
                    mma_bf16(d[1][nf], ah1, bl);
                    mma_bf16(d[0][nf], al0, bh);
                    mma_bf16(d[1][nf], al1, bh);
                }
            }
        }
        barg(barid);   // all group's atom2 (raw ea) reads complete

        // ---- E1: h_e epilogue -> silu -> split-store into atom2 ----
#pragma unroll
        for (int mb = 0; mb < 2; mb++)
#pragma unroll
            for (int nf = 0; nf < 2; nf++)
#pragma unroll
                for (int half = 0; half < 2; half++) {
                    int row = mbase + mb * 16 + gID + half * 8;
                    int col = nb1 + nf * 8 + 2 * tig;
                    float cm = crossms[row];
                    float v0 = dE[mb][nf][half * 2 + 0] + cm * w64s[col] + begs[col];
                    float v1 = dE[mb][nf][half * 2 + 1] + cm * w64s[col + 1] + begs[col + 1];
                    uint32_t o = sw(32768u +
                        (uint32_t)((row >> 3) * 1024 + (row & 7) * 128 + col * 2));
                    store_pair(AH, AL, o, siluf(v0), siluf(v1));
                }
        barg(barid);

        // ---- B2b: big GEMM kf 8..11 (atom 2 = h_e) ----
#pragma unroll
        for (int kf = 8; kf < 12; kf++) {
            uint32_t acol = (uint32_t)kf * 16 + acoll;
            uint32_t acp = (acol >> 6) * 16384 + (acol & 63) * 2;
            uint32_t ah0[4], ah1[4], al0[4], al1[4];
            ldsm4(ah0, sbase + OFF_AH + sw(arow[0] + acp));
            ldsm4(ah1, sbase + OFF_AH + sw(arow[1] + acp));
            ldsm4(al0, sbase + OFF_AL + sw(arow[0] + acp));
            ldsm4(al1, sbase + OFF_AL + sw(arow[1] + acp));
            uint32_t bcol = (uint32_t)kf * 16 + bk4;
            uint32_t bcp = (bcol >> 6) * 16384 + (bcol & 63) * 2;
#pragma unroll
            for (int p = 0; p < 2; p++) {
                uint32_t bh4[4], bl4[4];
                ldsm4(bh4, sbase + OFF_BH + sw(brow4[p] + bcp));
                ldsm4(bl4, sbase + OFF_BL + sw(brow4[p] + bcp));
#pragma unroll
                for (int sub = 0; sub < 2; sub++) {
                    int nf = 2 * p + sub;
                    uint32_t* bh = &bh4[2 * sub];
                    uint32_t* bl = &bl4[2 * sub];
                    mma_bf16(d[0][nf], ah0, bh);
                    mma_bf16(d[1][nf], ah1, bh);
                    mma_bf16(d[0][nf], ah0, bl);
                    mma_bf16(d[1][nf], ah1, bl);
                    mma_bf16(d[0][nf], al0, bh);
                    mma_bf16(d[1][nf], al1, bh);
                }
            }
        }

        // ---- C: fragment-native epilogue ----
#pragma unroll
        for (int mb = 0; mb < 2; mb++) {
#pragma unroll
            for (int half = 0; half < 2; half++) {
                int erow = mbase + mb * 16 + gID + half * 8;
                int ok = valid[erow];
                int dst = eRow[erow];
                float part = 0.0f;
#pragma unroll
                for (int nf = 0; nf < 4; nf++) {
                    int col = ncol * 32 + nf * 8 + 2 * tig;
                    float g0 = siluf(d[mb][nf][half * 2 + 0] + b1ps[col]);
                    float g1 = siluf(d[mb][nf][half * 2 + 1] + b1ps[col + 1]);
                    part += g0 * qs[col] + g1 * qs[col + 1];
                    if (ok) redv2(&g_z[(size_t)dst * 128 + col], g0, g1);
                }
                part += __shfl_xor_sync(0xffffffffu, part, 1);
                part += __shfl_xor_sync(0xffffffffu, part, 2);
                if (ok && tig == 0) {
                    float cf = qb4 + part;
                    reds(&g_vagg[dst * 3 + 0], evus[erow * 3 + 0] * cf);
                    reds(&g_vagg[dst * 3 + 1], evus[erow * 3 + 1] * cf);
                    reds(&g_vagg[dst * 3 + 2], evus[erow * 3 + 2] * cf);
                    if (ncol == 0) reds(&g_deg[dst], 1.0f);
                }
            }
        }
        barg(barid);  // protect this group's tiles + metadata before next tile
    }
}

// ---------------------------------------------------------------- node finalize
__global__ __launch_bounds__(256) void post_kernel(
    const float* __restrict__ s, const float* __restrict__ v,
    const float* __restrict__ mgw2, const float* __restrict__ mgb2,
    const float* __restrict__ upw, const float* __restrict__ upb,
    const float* __restrict__ lng, const float* __restrict__ lnb,
    float* __restrict__ outs, float* __restrict__ outv, int N) {
    __shared__ float mw2t[64][132];
    __shared__ float upwt[64][68];
    __shared__ float zs[4][132];
    __shared__ float xs[4][68];
    __shared__ float sn[4][68];
    const int tid = threadIdx.x;
    for (int idx = tid; idx < 128 * 64; idx += 256) {
        int k = idx >> 6, f = idx & 63;
        mw2t[f][k] = mgw2[idx];
    }
    for (int idx = tid; idx < 64 * 64; idx += 256) {
        int k = idx >> 6, f = idx & 63;
        upwt[f][k] = upw[idx];
    }
    __syncthreads();
    const int slot = tid >> 6, f = tid & 63;
    for (int n0 = blockIdx.x * 4; n0 < N; n0 += gridDim.x * 4) {
        int n = n0 + slot;
        bool ok = (n < N);
        zs[slot][f]      = ok ? g_z[n * 128 + f] : 0.0f;
        zs[slot][64 + f] = ok ? g_z[n * 128 + 64 + f] : 0.0f;
        __syncthreads();
        float degv = ok ? g_deg[n] : 0.0f;
        float acc = degv * mgb2[f];
#pragma unroll 4
        for (int k = 0; k < 128; k += 4) {
            float4 w = *(const float4*)&mw2t[f][k];
            float4 x = *(const float4*)&zs[slot][k];
            acc += w.x * x.x + w.y * x.y + w.z * x.z + w.w * x.w;
        }
        xs[slot][f] = siluf(acc);
        __syncthreads();
        float acc2 = upb[f];
#pragma unroll 4
        for (int k = 0; k < 64; k += 4) {
            float4 w = *(const float4*)&upwt[f][k];
            float4 x = *(const float4*)&xs[slot][k];
            acc2 += w.x * x.x + w.y * x.y + w.z * x.z + w.w * x.w;
        }
        float snew = ok ? (s[n * 64 + f] + acc2) : 0.0f;
        sn[slot][f] = snew;
        __syncthreads();
        float sum = 0.0f, sq = 0.0f;
#pragma unroll 4
        for (int k = 0; k < 64; k += 4) {
            float4 t = *(const float4*)&sn[slot][k];
            sum += t.x + t.y + t.z + t.w;
            sq += t.x * t.x + t.y * t.y + t.z * t.z + t.w * t.w;
        }
        float mu = sum * (1.0f / 64.0f);
        float var = sq * (1.0f / 64.0f) - mu * mu;
        if (ok) {
            outs[n * 64 + f] = (snew - mu) * rsqrtf(var + 1e-5f) * lng[f] + lnb[f];
            if (f < 3) {
                float v0 = v[n * 3 + 0] + g_vagg[n * 3 + 0];
                float v1 = v[n * 3 + 1] + g_vagg[n * 3 + 1];
                float v2 = v[n * 3 + 2] + g_vagg[n * 3 + 2];
                float nrm = sqrtf(v0 * v0 + v1 * v1 + v2 * v2);
                float inv = 1.0f / fmaxf(nrm, 1e-6f);
                float val = (f == 0) ? v0 : (f == 1) ? v1 : v2;
                outv[n * 3 + f] = val * inv;
            }
        }
        __syncthreads();
    }
}

// ---------------------------------------------------------------- launch
extern "C" void kernel_launch(void* const* d_in, const int* in_sizes, int n_in,
                              void* d_out, int out_size) {
    const float* s    = (const float*)d_in[0];
    const float* v    = (const float*)d_in[1];
    const int*   ei   = (const int*)d_in[2];
    const float* ea   = (const float*)d_in[3];
    const float* evu  = (const float*)d_in[4];
    const float* ngw1 = (const float*)d_in[5];
    const float* ngb1 = (const float*)d_in[6];
    const float* ngw2 = (const float*)d_in[7];
    const float* ngb2 = (const float*)d_in[8];
    const float* egw1 = (const float*)d_in[9];
    const float* egb1 = (const float*)d_in[10];
    const float* egw2 = (const float*)d_in[11];
    const float* egb2 = (const float*)d_in[12];
    const float* mgw1 = (const float*)d_in[13];
    const float* mgb1 = (const float*)d_in[14];
    const float* mgw2 = (const float*)d_in[15];
    const float* mgb2 = (const float*)d_in[16];
    const float* pew  = (const float*)d_in[17];
    const float* peb  = (const float*)d_in[18];
    const float* upw  = (const float*)d_in[19];
    const float* upb  = (const float*)d_in[20];
    const float* lng  = (const float*)d_in[21];
    const float* lnb  = (const float*)d_in[22];

    const int N = in_sizes[0] / 64;
    const int E = in_sizes[2] / 2;

    float* outs = (float*)d_out;
    float* outv = outs + (size_t)N * 64;

    int nsm = 148;
    cudaDeviceGetAttribute(&nsm, cudaDevAttrMultiProcessorCount, 0);

    zero_kernel<<<512, 256>>>(N * 128, N * 3, N);
    pre_kernel<<<1184, 256>>>(s, ngw1, N);
    preW_kernel<<<128, 256>>>(ngw2, ngb2, egw2, egb2, mgw1, mgb1, mgw2, mgb2, pew, peb);

    cudaFuncSetAttribute(edge_kernel, cudaFuncAttributeMaxDynamicSharedMemorySize,
                         EDGE_SMEM_TOTAL);
    edge_kernel<<<nsm, 512, EDGE_SMEM_TOTAL>>>(
        v, ei, ea, evu, ngw1, ngb1, egw1, egb1, N, E);

    post_kernel<<<1184, 256>>>(s, v, mgw2, mgb2, upw, upb, lng, lnb, outs, outv, N);
}

// round 16
// speedup vs baseline: 1.1214x; 1.1214x over previous
#include <cuda_runtime.h>
#include <cuda_bf16.h>
#include <stdint.h>
#include <math.h>

#define MAXN 50000
#define MAXE 800000

// ---- device scratch (allocation-free rule) ----
__device__ float g_P[MAXN * 64];      // s @ ng_w1[0:64]
__device__ float g_z[MAXN * 128];     // segsum(silu(hm))
__device__ float g_vagg[MAXN * 3];
__device__ float g_deg[MAXN];
__device__ float g_Wpt[128 * 192];    // fused W' transposed: [o][r]
__device__ float g_b1p[128];          // fused bias into hm
__device__ float g_q[128];            // mg_w2 @ pe_w
__device__ float g_qb[1];             // b_mg2 @ pe_w + pe_b

__device__ __forceinline__ float siluf(float x) { return x / (1.0f + __expf(-x)); }

__device__ __forceinline__ void reds(float* p, float v) {
    asm volatile("red.global.add.f32 [%0], %1;" :: "l"(p), "f"(v) : "memory");
}
__device__ __forceinline__ void redv2(float* p, float a, float b) {
    asm volatile("red.global.add.v2.f32 [%0], {%1,%2};"
                 :: "l"(p), "f"(a), "f"(b) : "memory");
}
__device__ __forceinline__ void barg(int id) {
    asm volatile("bar.sync %0, 128;" :: "r"(id) : "memory");
}

// ---- warp MMA helpers (sm_80+ vocabulary, safe on compute_103) ----
__device__ __forceinline__ uint32_t smem_u32(const void* p) {
    uint32_t a;
    asm("{ .reg .u64 t; cvta.to.shared.u64 t, %1; cvt.u32.u64 %0, t; }" : "=r"(a) : "l"(p));
    return a;
}
__device__ __forceinline__ void mma_bf16(float* d, const uint32_t* a, const uint32_t* b) {
    asm volatile(
        "mma.sync.aligned.m16n8k16.row.col.f32.bf16.bf16.f32 "
        "{%0,%1,%2,%3}, {%4,%5,%6,%7}, {%8,%9}, {%0,%1,%2,%3};"
        : "+f"(d[0]), "+f"(d[1]), "+f"(d[2]), "+f"(d[3])
        : "r"(a[0]), "r"(a[1]), "r"(a[2]), "r"(a[3]), "r"(b[0]), "r"(b[1]));
}
__device__ __forceinline__ void ldsm4(uint32_t* r, uint32_t addr) {
    asm volatile("ldmatrix.sync.aligned.m8n8.x4.shared.b16 {%0,%1,%2,%3}, [%4];"
                 : "=r"(r[0]), "=r"(r[1]), "=r"(r[2]), "=r"(r[3]) : "r"(addr));
}
__device__ __forceinline__ uint32_t sw(uint32_t b) { return b ^ ((b >> 3) & 0x70u); }

// blocked-atom SW128 byte offset in a [rows x cols] bf16 tile with 64-col atoms,
// 16 row-atoms per col-atom. atom = 8 rows x 64 cols (128B wide).
__device__ __forceinline__ uint32_t xoff(int row, int col) {
    uint32_t b = (uint32_t)((row >> 3) + (col >> 6) * 16) * 1024u
               + (uint32_t)(row & 7) * 128u + (uint32_t)(col & 63) * 2u;
    return sw(b);
}
// split-store an adjacent col pair (packed bf16x2, single STS.32 per tile)
__device__ __forceinline__ void store_pair(char* ah, char* al, uint32_t o, float x, float y) {
    __nv_bfloat162 h = __floats2bfloat162_rn(x, y);
    __nv_bfloat162 l = __floats2bfloat162_rn(x - __bfloat162float(h.x),
                                             y - __bfloat162float(h.y));
    *(__nv_bfloat162*)(ah + o) = h;
    *(__nv_bfloat162*)(al + o) = l;
}

// ---- smem layout (bytes) ----
#define OFF_AH 0           // X tile hi: 128 rows x 192 cols bf16 (3 col-atoms)
#define OFF_AL 49152
#define OFF_BH 98304       // W' tile hi: 128 out x 192 k bf16
#define OFF_BL 147456
#define OFF_EGBH 196608    // eg_w1 B-tile hi: 64 out x 64 k bf16 (8KB)
#define OFF_EGBL 204800
#define OFF_Q 212992       // float[128]
#define OFF_B1P 213504     // float[128]
#define OFF_W64S 214016    // float[64]  eg_w1 row 64 (cross coeff)
#define OFF_BEGS 214272    // float[64]  eg bias
#define OFF_W65 214528     // float[64]  ng_w1 row 64
#define OFF_BNG 214784     // float[64]  ng bias
#define OFF_RESI 215040    // float[128]
#define OFF_RESJ 215552
#define OFF_CROSS 216064   // float[128]
#define OFF_EVU 216576     // float[128][3]
#define OFF_EROW 218112    // int[128]
#define OFF_ECOL 218624    // int[128]
#define OFF_VALID 219136   // int[128]
#define OFF_QB 219648
#define EDGE_SMEM_TOTAL 219656

// ---------------------------------------------------------------- zero scratch
__global__ void zero_kernel(int n128, int n3, int n1) {
    int i = blockIdx.x * blockDim.x + threadIdx.x;
    int stride = gridDim.x * blockDim.x;
    for (int k = i; k < n128; k += stride) g_z[k] = 0.0f;
    for (int k = i; k < n3; k += stride) g_vagg[k] = 0.0f;
    for (int k = i; k < n1; k += stride) g_deg[k] = 0.0f;
}

// ---------------------------------------------------------------- P = s @ ng_w1[0:64,:]
__global__ __launch_bounds__(256) void pre_kernel(const float* __restrict__ s,
                                                  const float* __restrict__ ngw1, int N) {
    __shared__ float wt[64][68];
    __shared__ float xs[4][68];
    const int tid = threadIdx.x;
    for (int idx = tid; idx < 64 * 64; idx += 256) {
        int k = idx >> 6, f = idx & 63;
        wt[f][k] = ngw1[idx];
    }
    __syncthreads();
    const int slot = tid >> 6, f = tid & 63;
    for (int n0 = blockIdx.x * 4; n0 < N; n0 += gridDim.x * 4) {
        int n = n0 + slot;
        xs[slot][f] = (n < N) ? s[n * 64 + f] : 0.0f;
        __syncthreads();
        float acc = 0.0f;
#pragma unroll 4
        for (int k = 0; k < 64; k += 4) {
            float4 w = *(const float4*)&wt[f][k];
            float4 x = *(const float4*)&xs[slot][k];
            acc += w.x * x.x + w.y * x.y + w.z * x.z + w.w * x.w;
        }
        if (n < N) g_P[n * 64 + f] = acc;
        __syncthreads();
    }
}

// ---------------------------------------------------------------- fold weights
__global__ void preW_kernel(const float* __restrict__ ngw2, const float* __restrict__ ngb2,
                            const float* __restrict__ egw2, const float* __restrict__ egb2,
                            const float* __restrict__ mgw1, const float* __restrict__ mgb1,
                            const float* __restrict__ mgw2, const float* __restrict__ mgb2,
                            const float* __restrict__ pew, const float* __restrict__ peb) {
    int idx = blockIdx.x * blockDim.x + threadIdx.x;
    int stride = gridDim.x * blockDim.x;
    for (int t = idx; t < 128 * 192 + 128 + 128 + 1; t += stride) {
        if (t < 128 * 192) {
            int o = t / 192, r = t % 192;
            int seg = r >> 6, rr = r & 63, koff = seg * 64;
            const float* src = (seg < 2) ? ngw2 : egw2;
            float val = 0.0f;
            for (int k = 0; k < 64; k++)
                val += src[rr * 64 + k] * mgw1[(koff + k) * 128 + o];
            g_Wpt[o * 192 + r] = val;
        } else if (t < 128 * 192 + 128) {
            int o = t - 128 * 192;
            float val = mgb1[o];
            for (int k = 0; k < 64; k++) {
                val += ngb2[k] * (mgw1[k * 128 + o] + mgw1[(64 + k) * 128 + o]);
                val += egb2[k] * mgw1[(128 + k) * 128 + o];
            }
            g_b1p[o] = val;
        } else if (t < 128 * 192 + 256) {
            int o = t - 128 * 192 - 128;
            float val = 0.0f;
            for (int j = 0; j < 64; j++) val += mgw2[o * 64 + j] * pew[j];
            g_q[o] = val;
        } else {
            float val = peb[0];
            for (int j = 0; j < 64; j++) val += mgb2[j] * pew[j];
            g_qb[0] = val;
        }
    }
}

// ---------------------------------------------------------------- fused edge kernel
// Persistent CTA, 1024 threads = 8 independent 4-warp groups (named barrier 1+g).
// Group g owns edges [16g, 16g+16) of each 128-edge tile. Small per-warp tiles
// (16x32 B2) keep regs <= 64 so 32 warps/SM are resident (occ ~50%); 8 staggered
// groups hide each other's LDG/RED latency.
__global__ __launch_bounds__(1024, 1) void edge_kernel(
    const float* __restrict__ v, const int* __restrict__ ei,
    const float* __restrict__ ea, const float* __restrict__ evu,
    const float* __restrict__ ngw1, const float* __restrict__ ngb1,
    const float* __restrict__ egw1, const float* __restrict__ egb1,
    int N, int E) {
    extern __shared__ char smem[];
    char* AH = smem + OFF_AH;
    char* AL = smem + OFF_AL;
    float* qs = (float*)(smem + OFF_Q);
    float* b1ps = (float*)(smem + OFF_B1P);
    float* w64s = (float*)(smem + OFF_W64S);
    float* begs = (float*)(smem + OFF_BEGS);
    float* w65s = (float*)(smem + OFF_W65);
    float* bng = (float*)(smem + OFF_BNG);
    float* resIs = (float*)(smem + OFF_RESI);
    float* resJs = (float*)(smem + OFF_RESJ);
    float* crossms = (float*)(smem + OFF_CROSS);
    float* evus = (float*)(smem + OFF_EVU);
    int* eRow = (int*)(smem + OFF_EROW);
    int* eCol = (int*)(smem + OFF_ECOL);
    int* valid = (int*)(smem + OFF_VALID);
    float* qbp = (float*)(smem + OFF_QB);

    const int tid = threadIdx.x;
    const int lane = tid & 31;
    const int w = tid >> 5;
    const int L = lane;
    const uint32_t sbase = smem_u32(smem);

    // ---- one-time staging ----
    for (int idx = tid; idx < 128 * 192; idx += 1024) {
        int o = idx / 192, r = idx % 192;
        float val = g_Wpt[idx];
        uint32_t off = xoff(o, r);
        __nv_bfloat16 h = __float2bfloat16(val);
        *(__nv_bfloat16*)(smem + OFF_BH + off) = h;
        *(__nv_bfloat16*)(smem + OFF_BL + off) = __float2bfloat16(val - __bfloat162float(h));
    }
    for (int idx = tid; idx < 64 * 64; idx += 1024) {
        int k = idx >> 6, n = idx & 63;
        float val = egw1[k * 64 + n];   // B[n][k] = W1[k][n]
        uint32_t off = sw((uint32_t)((n >> 3) * 1024 + (n & 7) * 128 + k * 2));
        __nv_bfloat16 h = __float2bfloat16(val);
        *(__nv_bfloat16*)(smem + OFF_EGBH + off) = h;
        *(__nv_bfloat16*)(smem + OFF_EGBL + off) = __float2bfloat16(val - __bfloat162float(h));
    }
    if (tid < 64) {
        w64s[tid] = egw1[64 * 64 + tid];
        begs[tid] = egb1[tid];
        w65s[tid] = ngw1[64 * 64 + tid];
        bng[tid] = ngb1[tid];
    } else if (tid < 192) {
        b1ps[tid - 64] = g_b1p[tid - 64];
    } else if (tid < 320) {
        qs[tid - 192] = g_q[tid - 192];
    } else if (tid == 320) {
        qbp[0] = g_qb[0];
    }
    __syncthreads();

    // group decomposition: 8 groups x 4 warps
    const int g = w >> 2;            // 0..7
    const int wh = w & 3;            // warp within group
    const int g16 = g * 16;
    const int barid = 1 + g;

    // hoisted per-lane constants (phase A)
    const float w65a = w65s[2 * L], w65b = w65s[2 * L + 1];
    const float bna = bng[2 * L], bnb = bng[2 * L + 1];

    // warp-tile constants
    const int mbase = g16;                   // all 4 warps share the group's 16 edges
    const int ncol = wh;                     // B2: N group of 32
    const int nb1 = wh * 16;                 // B1: N group of 16
    const int gID = lane >> 2, tig = lane & 3;
    const int g8 = lane >> 3;
    uint32_t arow;
    {
        int row = mbase + (lane & 15);
        arow = (uint32_t)((row >> 3) * 1024 + (row & 7) * 128);
    }
    const uint32_t acoll = (uint32_t)((lane >> 4) * 8);
    uint32_t brow4[2];
#pragma unroll
    for (int p = 0; p < 2; p++) {
        int row = ncol * 32 + p * 16 + (g8 >> 1) * 8 + (lane & 7);
        brow4[p] = (uint32_t)((row >> 3) * 1024 + (row & 7) * 128);
    }
    const uint32_t bk4 = (uint32_t)((g8 & 1) * 8);
    uint32_t browE4;
    {
        int nrow = nb1 + (g8 >> 1) * 8 + (lane & 7);
        browE4 = (uint32_t)((nrow >> 3) * 1024 + (nrow & 7) * 128);
    }
    const float qb4 = 0.25f * qbp[0];
    const int stride = gridDim.x * 128;
    const int erow0 = g16 + wh * 4;          // this warp's first edge row

    for (int base = blockIdx.x * 128; base < E; base += stride) {
        // ---- P0 (warp-local): metadata for this warp's 4 edges ----
        if (L < 4) {
            int erow = erow0 + L;
            int e = base + erow;
            int ok = (e < E);
            int r = 0, c = 0;
            float rI = 0.f, rJ = 0.f, cm = 0.f, u0 = 0.f, u1 = 0.f, u2 = 0.f;
            if (ok) {
                r = ei[e]; c = ei[E + e];
                float vx = v[r * 3 + 0], vy = v[r * 3 + 1], vz = v[r * 3 + 2];
                float wx = v[c * 3 + 0], wy = v[c * 3 + 1], wz = v[c * 3 + 2];
                u0 = evu[e * 3 + 0]; u1 = evu[e * 3 + 1]; u2 = evu[e * 3 + 2];
                rI = 1.0f - (vx * u0 + vy * u1 + vz * u2);
                rJ = 1.0f + (wx * u0 + wy * u1 + wz * u2);
                float cx = vy * wz - vz * wy;
                float cy = vz * wx - vx * wz;
                float cz = vx * wy - vy * wx;
                cm = sqrtf(cx * cx + cy * cy + cz * cz);
            }
            valid[erow] = ok;
            eRow[erow] = r;
            eCol[erow] = c;
            resIs[erow] = rI; resJs[erow] = rJ; crossms[erow] = cm;
            evus[erow * 3 + 0] = u0;
            evus[erow * 3 + 1] = u1;
            evus[erow * 3 + 2] = u2;
        }
        __syncwarp();

        // ---- A1: stage ea into X atom2 + h_i/h_j into atoms 0/1 ----
#pragma unroll
        for (int j = 0; j < 4; j++) {
            int erow = erow0 + j;
            int e = base + erow;
            float2 a = make_float2(0.f, 0.f);
            if (e < E) a = *(const float2*)&ea[(size_t)e * 64 + 2 * L];
            uint32_t o = sw(32768u + (uint32_t)((erow >> 3) * 1024 + (erow & 7) * 128 + 4 * L));
            store_pair(AH, AL, o, a.x, a.y);
        }
#pragma unroll
        for (int j = 0; j < 4; j++) {
            int erow = erow0 + j;
            int ok = valid[erow];
            float2 pi = make_float2(0.f, 0.f), pj = pi;
            if (ok) {
                int r = eRow[erow], c = eCol[erow];
                pi = *(const float2*)&g_P[r * 64 + 2 * L];
                pj = *(const float2*)&g_P[c * 64 + 2 * L];
            }
            float rI = resIs[erow], rJ = resJs[erow];
            float i0 = siluf(pi.x + rI * w65a + bna);
            float i1 = siluf(pi.y + rI * w65b + bnb);
            float j0v = siluf(pj.x + rJ * w65a + bna);
            float j1v = siluf(pj.y + rJ * w65b + bnb);
            uint32_t ro = (uint32_t)((erow >> 3) * 1024 + (erow & 7) * 128 + 4 * L);
            store_pair(AH, AL, sw(ro), i0, i1);
            store_pair(AH, AL, sw(16384u + ro), j0v, j1v);
        }
        barg(barid);

        // ---- B1: h_e MMA (16 edges x 16 out-cols, K=64, 3 split terms) ----
        float dE[2][4];
#pragma unroll
        for (int nf = 0; nf < 2; nf++)
#pragma unroll
            for (int i = 0; i < 4; i++) dE[nf][i] = 0.0f;
#pragma unroll
        for (int kf = 0; kf < 4; kf++) {
            uint32_t ac2 = (uint32_t)(kf * 16 + acoll) * 2;
            uint32_t ah0[4], al0[4];
            ldsm4(ah0, sbase + OFF_AH + sw(32768u + arow + ac2));
            ldsm4(al0, sbase + OFF_AL + sw(32768u + arow + ac2));
            uint32_t bc2 = (uint32_t)(kf * 16 + bk4) * 2;
            uint32_t bh4[4], bl4[4];
            ldsm4(bh4, sbase + OFF_EGBH + sw(browE4 + bc2));
            ldsm4(bl4, sbase + OFF_EGBL + sw(browE4 + bc2));
#pragma unroll
            for (int sub = 0; sub < 2; sub++) {
                uint32_t* bh = &bh4[2 * sub];
                uint32_t* bl = &bl4[2 * sub];
                mma_bf16(dE[sub], ah0, bh);
                mma_bf16(dE[sub], ah0, bl);
                mma_bf16(dE[sub], al0, bh);
            }
        }
        barg(barid);   // this group's reads of atom2 (raw ea) complete

        // ---- E1: h_e epilogue -> silu -> split-store into atom2 ----
#pragma unroll
        for (int nf = 0; nf < 2; nf++)
#pragma unroll
            for (int half = 0; half < 2; half++) {
                int row = mbase + gID + half * 8;
                int col = nb1 + nf * 8 + 2 * tig;
                float cm = crossms[row];
                float v0 = dE[nf][half * 2 + 0] + cm * w64s[col] + begs[col];
                float v1 = dE[nf][half * 2 + 1] + cm * w64s[col + 1] + begs[col + 1];
                uint32_t o = sw(32768u +
                    (uint32_t)((row >> 3) * 1024 + (row & 7) * 128 + col * 2));
                store_pair(AH, AL, o, siluf(v0), siluf(v1));
            }
        barg(barid);

        // ---- B2: big GEMM (16 edges x 32 cols, K=192, 3 terms, fused) ----
        float d[4][4];
#pragma unroll
        for (int nf = 0; nf < 4; nf++)
#pragma unroll
            for (int i = 0; i < 4; i++) d[nf][i] = 0.0f;
#pragma unroll
        for (int kf = 0; kf < 12; kf++) {
            uint32_t acol = (uint32_t)kf * 16 + acoll;
            uint32_t acp = (acol >> 6) * 16384 + (acol & 63) * 2;
            uint32_t ah0[4], al0[4];
            ldsm4(ah0, sbase + OFF_AH + sw(arow + acp));
            ldsm4(al0, sbase + OFF_AL + sw(arow + acp));
            uint32_t bcol = (uint32_t)kf * 16 + bk4;
            uint32_t bcp = (bcol >> 6) * 16384 + (bcol & 63) * 2;
#pragma unroll
            for (int p = 0; p < 2; p++) {
                uint32_t bh4[4], bl4[4];
                ldsm4(bh4, sbase + OFF_BH + sw(brow4[p] + bcp));
                ldsm4(bl4, sbase + OFF_BL + sw(brow4[p] + bcp));
#pragma unroll
                for (int sub = 0; sub < 2; sub++) {
                    int nf = 2 * p + sub;
                    uint32_t* bh = &bh4[2 * sub];
                    uint32_t* bl = &bl4[2 * sub];
                    mma_bf16(d[nf], ah0, bh);
                    mma_bf16(d[nf], ah0, bl);
                    mma_bf16(d[nf], al0, bh);
                }
            }
        }

        // ---- C: fragment-native epilogue ----
#pragma unroll
        for (int half = 0; half < 2; half++) {
            int erow = mbase + gID + half * 8;
            int ok = valid[erow];
            int dst = eRow[erow];
            float part = 0.0f;
#pragma unroll
            for (int nf = 0; nf < 4; nf++) {
                int col = ncol * 32 + nf * 8 + 2 * tig;
                float g0 = siluf(d[nf][half * 2 + 0] + b1ps[col]);
                float g1 = siluf(d[nf][half * 2 + 1] + b1ps[col + 1]);
                part += g0 * qs[col] + g1 * qs[col + 1];
                if (ok) redv2(&g_z[(size_t)dst * 128 + col], g0, g1);
            }
            part += __shfl_xor_sync(0xffffffffu, part, 1);
            part += __shfl_xor_sync(0xffffffffu, part, 2);
            if (ok && tig == 0) {
                float cf = qb4 + part;
                reds(&g_vagg[dst * 3 + 0], evus[erow * 3 + 0] * cf);
                reds(&g_vagg[dst * 3 + 1], evus[erow * 3 + 1] * cf);
                reds(&g_vagg[dst * 3 + 2], evus[erow * 3 + 2] * cf);
                if (ncol == 0) reds(&g_deg[dst], 1.0f);
            }
        }
        barg(barid);  // protect this group's tiles + metadata before next tile
    }
}

// ---------------------------------------------------------------- node finalize
__global__ __launch_bounds__(256) void post_kernel(
    const float* __restrict__ s, const float* __restrict__ v,
    const float* __restrict__ mgw2, const float* __restrict__ mgb2,
    const float* __restrict__ upw, const float* __restrict__ upb,
    const float* __restrict__ lng, const float* __restrict__ lnb,
    float* __restrict__ outs, float* __restrict__ outv, int N) {
    __shared__ float mw2t[64][132];
    __shared__ float upwt[64][68];
    __shared__ float zs[4][132];
    __shared__ float xs[4][68];
    __shared__ float sn[4][68];
    const int tid = threadIdx.x;
    for (int idx = tid; idx < 128 * 64; idx += 256) {
        int k = idx >> 6, f = idx & 63;
        mw2t[f][k] = mgw2[idx];
    }
    for (int idx = tid; idx < 64 * 64; idx += 256) {
        int k = idx >> 6, f = idx & 63;
        upwt[f][k] = upw[idx];
    }
    __syncthreads();
    const int slot = tid >> 6, f = tid & 63;
    for (int n0 = blockIdx.x * 4; n0 < N; n0 += gridDim.x * 4) {
        int n = n0 + slot;
        bool ok = (n < N);
        zs[slot][f]      = ok ? g_z[n * 128 + f] : 0.0f;
        zs[slot][64 + f] = ok ? g_z[n * 128 + 64 + f] : 0.0f;
        __syncthreads();
        float degv = ok ? g_deg[n] : 0.0f;
        float acc = degv * mgb2[f];
#pragma unroll 4
        for (int k = 0; k < 128; k += 4) {
            float4 w = *(const float4*)&mw2t[f][k];
            float4 x = *(const float4*)&zs[slot][k];
            acc += w.x * x.x + w.y * x.y + w.z * x.z + w.w * x.w;
        }
        xs[slot][f] = siluf(acc);
        __syncthreads();
        float acc2 = upb[f];
#pragma unroll 4
        for (int k = 0; k < 64; k += 4) {
            float4 w = *(const float4*)&upwt[f][k];
            float4 x = *(const float4*)&xs[slot][k];
            acc2 += w.x * x.x + w.y * x.y + w.z * x.z + w.w * x.w;
        }
        float snew = ok ? (s[n * 64 + f] + acc2) : 0.0f;
        sn[slot][f] = snew;
        __syncthreads();
        float sum = 0.0f, sq = 0.0f;
#pragma unroll 4
        for (int k = 0; k < 64; k += 4) {
            float4 t = *(const float4*)&sn[slot][k];
            sum += t.x + t.y + t.z + t.w;
            sq += t.x * t.x + t.y * t.y + t.z * t.z + t.w * t.w;
        }
        float mu = sum * (1.0f / 64.0f);
        float var = sq * (1.0f / 64.0f) - mu * mu;
        if (ok) {
            outs[n * 64 + f] = (snew - mu) * rsqrtf(var + 1e-5f) * lng[f] + lnb[f];
            if (f < 3) {
                float v0 = v[n * 3 + 0] + g_vagg[n * 3 + 0];
                float v1 = v[n * 3 + 1] + g_vagg[n * 3 + 1];
                float v2 = v[n * 3 + 2] + g_vagg[n * 3 + 2];
                float nrm = sqrtf(v0 * v0 + v1 * v1 + v2 * v2);
                float inv = 1.0f / fmaxf(nrm, 1e-6f);
                float val = (f == 0) ? v0 : (f == 1) ? v1 : v2;
                outv[n * 3 + f] = val * inv;
            }
        }
        __syncthreads();
    }
}

// ---------------------------------------------------------------- launch
extern "C" void kernel_launch(void* const* d_in, const int* in_sizes, int n_in,
                              void* d_out, int out_size) {
    const float* s    = (const float*)d_in[0];
    const float* v    = (const float*)d_in[1];
    const int*   ei   = (const int*)d_in[2];
    const float* ea   = (const float*)d_in[3];
    const float* evu  = (const float*)d_in[4];
    const float* ngw1 = (const float*)d_in[5];
    const float* ngb1 = (const float*)d_in[6];
    const float* ngw2 = (const float*)d_in[7];
    const float* ngb2 = (const float*)d_in[8];
    const float* egw1 = (const float*)d_in[9];
    const float* egb1 = (const float*)d_in[10];
    const float* egw2 = (const float*)d_in[11];
    const float* egb2 = (const float*)d_in[12];
    const float* mgw1 = (const float*)d_in[13];
    const float* mgb1 = (const float*)d_in[14];
    const float* mgw2 = (const float*)d_in[15];
    const float* mgb2 = (const float*)d_in[16];
    const float* pew  = (const float*)d_in[17];
    const float* peb  = (const float*)d_in[18];
    const float* upw  = (const float*)d_in[19];
    const float* upb  = (const float*)d_in[20];
    const float* lng  = (const float*)d_in[21];
    const float* lnb  = (const float*)d_in[22];

    const int N = in_sizes[0] / 64;
    const int E = in_sizes[2] / 2;

    float* outs = (float*)d_out;
    float* outv = outs + (size_t)N * 64;

    int nsm = 148;
    cudaDeviceGetAttribute(&nsm, cudaDevAttrMultiProcessorCount, 0);

    zero_kernel<<<512, 256>>>(N * 128, N * 3, N);
    pre_kernel<<<1184, 256>>>(s, ngw1, N);
    preW_kernel<<<128, 256>>>(ngw2, ngb2, egw2, egb2, mgw1, mgb1, mgw2, mgb2, pew, peb);

    cudaFuncSetAttribute(edge_kernel, cudaFuncAttributeMaxDynamicSharedMemorySize,
                         EDGE_SMEM_TOTAL);
    edge_kernel<<<nsm, 1024, EDGE_SMEM_TOTAL>>>(
        v, ei, ea, evu, ngw1, ngb1, egw1, egb1, N, E);

    post_kernel<<<1184, 256>>>(s, v, mgw2, mgb2, upw, upb, lng, lnb, outs, outv, N);
}